// round 11
// baseline (speedup 1.0000x reference)
#include <cuda_runtime.h>

// Dynamic local filtering: out[n,c,h,w] = sum_{k1,k2} x_pad[n,c,h+k1,w+k2] * kern[n,(c*25+k1*5+k2),h,w]
// then leaky_relu(0.2). Replicate padding. Shapes fixed: N=4, C=8, H=W=256, K=5.
// R8: R6 base (full-width 256x4 tiles, 4px/thread LDG.128, contiguous 4KB/tap,
//     256-thread CTAs) with a 3-stage 9/8/8 pipelined weight preload so load
//     issue overlaps FMA consumption through the whole body (no dead-tail).

#define WID 256
#define HEI 256
#define HW  (WID * HEI)
#define TW  256   // full width: 64 threads x 4 px per row
#define TH  4     // rows per CTA
#define SW  (TW + 4)   // 260 floats per smem row (float4-aligned)
#define SH  (TH + 4)   // 8

__global__ __launch_bounds__(256)
void dynconv5x5_kernel(const float* __restrict__ x,
                       const float* __restrict__ kern,
                       float* __restrict__ out)
{
    __shared__ float tile[SH * SW];

    const int plane = blockIdx.z;           // n*C + c, 0..31
    const int by = blockIdx.y * TH;
    const int tid = threadIdx.x;            // 0..255

    const int lx = tid & 63;                // 64 threads across the row
    const int ly = tid >> 6;                // 4 rows
    const int w0 = lx * 4;                  // first of 4 pixels handled
    const int h  = by + ly;

    // Weight pointer: per tap t, this thread's 4 pixels' weights are one float4.
    const float4* __restrict__ k4 = (const float4*)kern
        + (size_t)plane * 25 * (HW / 4)
        + (size_t)(h * WID + w0) / 4;

    // ---- Stage 0: issue taps 0..8 (9 LDG.128 in flight) ----
    float4 kva[9];
    #pragma unroll
    for (int t = 0; t < 9; t++) {
        kva[t] = __ldcs(&k4[(size_t)t * (HW / 4)]);
    }

    // Cooperative load of x tile with halo; replicate padding via clamp.
    // (Overlaps with the in-flight weight loads; halo re-reads are L2 hits.)
    const float* __restrict__ xp = x + (size_t)plane * HW;
    #pragma unroll
    for (int i = tid; i < SH * SW; i += 256) {
        int sy = i / SW;
        int sx = i - sy * SW;
        int gy = by + sy - 2; gy = max(0, min(HEI - 1, gy));
        int gx = sx - 2;      gx = max(0, min(WID - 1, gx));
        tile[i] = xp[gy * WID + gx];
    }
    __syncthreads();

    float ax = 0.f, ay = 0.f, az = 0.f, aw = 0.f;

    // Stage the 8-wide x windows for all 5 dy rows once (smem -> regs).
    float s[5][8];
    #pragma unroll
    for (int dy = 0; dy < 5; dy++) {
        const float4* srow = (const float4*)&tile[(ly + dy) * SW + w0];
        float4 s0 = srow[0];
        float4 s1 = srow[1];
        s[dy][0] = s0.x; s[dy][1] = s0.y; s[dy][2] = s0.z; s[dy][3] = s0.w;
        s[dy][4] = s1.x; s[dy][5] = s1.y; s[dy][6] = s1.z; s[dy][7] = s1.w;
    }

    // ---- Stage 1: issue taps 9..16 while consuming taps 0..8 ----
    asm volatile("" ::: "memory");
    float4 kvb[8];
    #pragma unroll
    for (int t = 0; t < 8; t++) {
        kvb[t] = __ldcs(&k4[(size_t)(t + 9) * (HW / 4)]);
    }

    #pragma unroll
    for (int t = 0; t < 9; t++) {
        int dy = t / 5, dx = t % 5;
        float4 w = kva[t];
        ax += w.x * s[dy][dx + 0];
        ay += w.y * s[dy][dx + 1];
        az += w.z * s[dy][dx + 2];
        aw += w.w * s[dy][dx + 3];
    }

    // ---- Stage 2: issue taps 17..24 while consuming taps 9..16 ----
    asm volatile("" ::: "memory");
    float4 kvc[8];
    #pragma unroll
    for (int t = 0; t < 8; t++) {
        kvc[t] = __ldcs(&k4[(size_t)(t + 17) * (HW / 4)]);
    }

    #pragma unroll
    for (int t = 9; t < 17; t++) {
        int dy = t / 5, dx = t % 5;
        float4 w = kvb[t - 9];
        ax += w.x * s[dy][dx + 0];
        ay += w.y * s[dy][dx + 1];
        az += w.z * s[dy][dx + 2];
        aw += w.w * s[dy][dx + 3];
    }

    // ---- Stage 3: consume taps 17..24 ----
    asm volatile("" ::: "memory");
    #pragma unroll
    for (int t = 17; t < 25; t++) {
        int dy = t / 5, dx = t % 5;
        float4 w = kvc[t - 17];
        ax += w.x * s[dy][dx + 0];
        ay += w.y * s[dy][dx + 1];
        az += w.z * s[dy][dx + 2];
        aw += w.w * s[dy][dx + 3];
    }

    // leaky_relu(0.2)
    ax = ax >= 0.f ? ax : 0.2f * ax;
    ay = ay >= 0.f ? ay : 0.2f * ay;
    az = az >= 0.f ? az : 0.2f * az;
    aw = aw >= 0.f ? aw : 0.2f * aw;

    float4 r = make_float4(ax, ay, az, aw);
    __stcs(&((float4*)out)[(size_t)plane * (HW / 4) + (size_t)(h * WID + w0) / 4], r);
}

extern "C" void kernel_launch(void* const* d_in, const int* in_sizes, int n_in,
                              void* d_out, int out_size)
{
    const float* x    = (const float*)d_in[0];   // (4, 8, 256, 256)
    const float* kern = (const float*)d_in[1];   // (4, 200, 256, 256)
    float* out = (float*)d_out;                  // (4, 8, 256, 256)

    dim3 block(256, 1, 1);
    dim3 grid(1, HEI / TH, 32);                  // (1, 64, 32) = 2048 CTAs
    dynconv5x5_kernel<<<grid, block>>>(x, kern, out);
}